// round 6
// baseline (speedup 1.0000x reference)
#include <cuda_runtime.h>
#include <float.h>

#define N_Q   4096
#define M_P   32768
#define W_F   768
#define K_NN  4
#define R2    0.25f

#define BM 128
#define BN 64
#define BK 16

// Scratch (no allocation allowed).
__device__ int    g_idx[N_Q * K_NN];
__device__ float  g_aggraw[N_Q * W_F];
__device__ float4 g_pts4[M_P];          // packed {x, y, z, pp}

__device__ __forceinline__ bool pair_less(float d1, int i1, float d2, int i2) {
    return (d1 < d2) || (d1 == d2 && i1 < i2);
}

// ---------------------------------------------------------------------------
// Kernel 0: pack pts -> {x,y,z,pp}, pp in the exact reference association:
//   pp = fma(x,x, fma(y,y, rn(z*z)))   (descending FMA — validated R5)
// ---------------------------------------------------------------------------
__global__ __launch_bounds__(256) void pack_kernel(const float* __restrict__ pts) {
    const int j = blockIdx.x * 256 + threadIdx.x;
    if (j < M_P) {
        const float px = pts[j * 3 + 0];
        const float py = pts[j * 3 + 1];
        const float pz = pts[j * 3 + 2];
        const float pp = __fmaf_rn(px, px, __fmaf_rn(py, py, __fmul_rn(pz, pz)));
        g_pts4[j] = make_float4(px, py, pz, pp);
    }
}

// ---------------------------------------------------------------------------
// Kernel 1: top-4 nearest neighbors per query. Arithmetic frozen (R5-exact):
//   qq  = fma(x,x, fma(y,y, rn(z*z)))      (descending FMA)
//   dot = fma(qz,pz, fma(qy,py, rn(qx*px))) (ascending FMA)
//   d2  = rn(rn(qq+pp) - rn(2*dot))
// Now one LDG.128 per point + x4 unroll.
// ---------------------------------------------------------------------------
__global__ __launch_bounds__(256) void topk_kernel(const float* __restrict__ q_pos) {
    const int n   = blockIdx.x;
    const int tid = threadIdx.x;

    const float qx = q_pos[n * 3 + 0];
    const float qy = q_pos[n * 3 + 1];
    const float qz = q_pos[n * 3 + 2];
    const float qq = __fmaf_rn(qx, qx, __fmaf_rn(qy, qy, __fmul_rn(qz, qz)));

    float bd[4] = {FLT_MAX, FLT_MAX, FLT_MAX, FLT_MAX};
    int   bi[4] = {-1, -1, -1, -1};

    // 128 points per thread, unrolled x4 for MLP.
    #pragma unroll 1
    for (int it = 0; it < M_P / (256 * 4); it++) {
        const int jb = it * (256 * 4) + tid;
        float4 p[4];
        #pragma unroll
        for (int u = 0; u < 4; u++) p[u] = g_pts4[jb + u * 256];

        #pragma unroll
        for (int u = 0; u < 4; u++) {
            const int j = jb + u * 256;
            float dot = __fmul_rn(qx, p[u].x);
            dot = __fmaf_rn(qy, p[u].y, dot);
            dot = __fmaf_rn(qz, p[u].z, dot);
            const float t1 = __fadd_rn(qq, p[u].w);
            const float d2 = __fadd_rn(t1, -__fmul_rn(2.0f, dot));
            if (pair_less(d2, j, bd[3], bi[3])) {
                bd[3] = d2; bi[3] = j;
                #pragma unroll
                for (int q = 3; q > 0; --q) {
                    if (pair_less(bd[q], bi[q], bd[q - 1], bi[q - 1])) {
                        float td = bd[q]; bd[q] = bd[q - 1]; bd[q - 1] = td;
                        int   ti = bi[q]; bi[q] = bi[q - 1]; bi[q - 1] = ti;
                    }
                }
            }
        }
    }

    __shared__ float sd[256 * 4];
    __shared__ int   si[256 * 4];
    #pragma unroll
    for (int k = 0; k < 4; k++) { sd[tid * 4 + k] = bd[k]; si[tid * 4 + k] = bi[k]; }
    __syncthreads();

    // Tree merge of sorted 4-lists.
    for (int s = 128; s > 0; s >>= 1) {
        if (tid < s) {
            float ad[4], xd[4]; int ai[4], xi[4];
            #pragma unroll
            for (int k = 0; k < 4; k++) {
                ad[k] = sd[tid * 4 + k];        ai[k] = si[tid * 4 + k];
                xd[k] = sd[(tid + s) * 4 + k];  xi[k] = si[(tid + s) * 4 + k];
            }
            float rd[4]; int ri[4];
            int ia = 0, ib = 0;
            #pragma unroll
            for (int t = 0; t < 4; t++) {
                bool takeA = pair_less(ad[ia], ai[ia], xd[ib], xi[ib]);
                rd[t] = takeA ? ad[ia] : xd[ib];
                ri[t] = takeA ? ai[ia] : xi[ib];
                if (takeA) ia++; else ib++;
            }
            #pragma unroll
            for (int k = 0; k < 4; k++) { sd[tid * 4 + k] = rd[k]; si[tid * 4 + k] = ri[k]; }
        }
        __syncthreads();
    }

    if (tid == 0) {
        #pragma unroll
        for (int k = 0; k < 4; k++)
            g_idx[n * 4 + k] = (sd[k] <= R2) ? si[k] : -1;   // radius mask
    }
}

// ---------------------------------------------------------------------------
// Kernel 2: gathered SGEMM (unchanged — at ~95% of fp32 FFMA roofline).
// ---------------------------------------------------------------------------
__global__ __launch_bounds__(256) void gemm_kernel(const float* __restrict__ feats,
                                                   const float* __restrict__ Wagg,
                                                   const float* __restrict__ bagg) {
    __shared__ float As[BK][BM];
    __shared__ float Bs[BK][BN];
    __shared__ int   sidx[BM][4];

    const int tid = threadIdx.x;
    const int bm  = blockIdx.y * BM;
    const int bn  = blockIdx.x * BN;

    for (int t = tid; t < BM * 4; t += 256)
        sidx[t >> 2][t & 3] = g_idx[(bm + (t >> 2)) * 4 + (t & 3)];
    __syncthreads();

    float acc[8][4];
    #pragma unroll
    for (int r = 0; r < 8; r++)
        #pragma unroll
        for (int c = 0; c < 4; c++) acc[r][c] = 0.0f;

    const int rg = tid >> 4;
    const int cg = tid & 15;

    for (int kt = 0; kt < K_NN * W_F; kt += BK) {
        const int kidx  = kt / W_F;
        const int wbase = kt - kidx * W_F;

        #pragma unroll
        for (int v = 0; v < 2; v++) {
            const int s2  = tid + v * 256;
            const int row = s2 >> 2;
            const int kk  = (s2 & 3) << 2;
            const int prow = sidx[row][kidx];
            float4 a = make_float4(0.f, 0.f, 0.f, 0.f);
            if (prow >= 0)
                a = *reinterpret_cast<const float4*>(&feats[prow * W_F + wbase + kk]);
            As[kk + 0][row] = a.x;
            As[kk + 1][row] = a.y;
            As[kk + 2][row] = a.z;
            As[kk + 3][row] = a.w;
        }
        {
            const int kkb = tid >> 4;
            const int jb  = (tid & 15) << 2;
            float4 b = *reinterpret_cast<const float4*>(&Wagg[(kt + kkb) * W_F + bn + jb]);
            *reinterpret_cast<float4*>(&Bs[kkb][jb]) = b;
        }
        __syncthreads();

        #pragma unroll
        for (int kk = 0; kk < BK; kk++) {
            float4 a0 = *reinterpret_cast<const float4*>(&As[kk][rg * 8 + 0]);
            float4 a1 = *reinterpret_cast<const float4*>(&As[kk][rg * 8 + 4]);
            float4 bv = *reinterpret_cast<const float4*>(&Bs[kk][cg * 4]);
            const float ar[8] = {a0.x, a0.y, a0.z, a0.w, a1.x, a1.y, a1.z, a1.w};
            const float br[4] = {bv.x, bv.y, bv.z, bv.w};
            #pragma unroll
            for (int r = 0; r < 8; r++)
                #pragma unroll
                for (int c = 0; c < 4; c++)
                    acc[r][c] += ar[r] * br[c];
        }
        __syncthreads();
    }

    #pragma unroll
    for (int r = 0; r < 8; r++) {
        const int grow = bm + rg * 8 + r;
        const int gcol = bn + cg * 4;
        float4 o;
        o.x = acc[r][0] + bagg[gcol + 0];
        o.y = acc[r][1] + bagg[gcol + 1];
        o.z = acc[r][2] + bagg[gcol + 2];
        o.w = acc[r][3] + bagg[gcol + 3];
        *reinterpret_cast<float4*>(&g_aggraw[grow * W_F + gcol]) = o;
    }
}

// ---------------------------------------------------------------------------
// Kernel 3: pos embedding GEMV (K=6) + two LayerNorms + add.
// ---------------------------------------------------------------------------
__device__ __forceinline__ float block_sum(float v, float* sbuf) {
    __syncthreads();
    #pragma unroll
    for (int o = 16; o > 0; o >>= 1) v += __shfl_xor_sync(0xffffffffu, v, o);
    const int wid = threadIdx.x >> 5, lane = threadIdx.x & 31;
    if (lane == 0) sbuf[wid] = v;
    __syncthreads();
    if (wid == 0) {
        float x = (lane < 8) ? sbuf[lane] : 0.0f;
        #pragma unroll
        for (int o = 4; o > 0; o >>= 1) x += __shfl_xor_sync(0xffffffffu, x, o);
        if (lane == 0) sbuf[0] = x;
    }
    __syncthreads();
    return sbuf[0];
}

__global__ __launch_bounds__(256) void ln_kernel(const float* __restrict__ pos_in,
                                                 const float* __restrict__ Wpos,
                                                 const float* __restrict__ bpos,
                                                 const float* __restrict__ gagg,
                                                 const float* __restrict__ beagg,
                                                 const float* __restrict__ gpos,
                                                 const float* __restrict__ bepos,
                                                 float* __restrict__ out) {
    const int n   = blockIdx.x;
    const int tid = threadIdx.x;
    __shared__ float pin[6];
    __shared__ float sred[32];
    if (tid < 6) pin[tid] = pos_in[n * 6 + tid];
    __syncthreads();

    float a[3], p[3];
    float sa = 0.f, sp = 0.f;
    #pragma unroll
    for (int t = 0; t < 3; t++) {
        const int j = tid + t * 256;
        a[t] = g_aggraw[n * W_F + j];
        float pv = bpos[j];
        #pragma unroll
        for (int i = 0; i < 6; i++) pv += pin[i] * Wpos[i * W_F + j];
        p[t] = pv;
        sa += a[t]; sp += p[t];
    }
    const float ma = block_sum(sa, sred) * (1.0f / 768.0f);
    const float mp = block_sum(sp, sred) * (1.0f / 768.0f);

    float va = 0.f, vp = 0.f;
    #pragma unroll
    for (int t = 0; t < 3; t++) {
        const float da = a[t] - ma; va += da * da;
        const float dp = p[t] - mp; vp += dp * dp;
    }
    va = block_sum(va, sred) * (1.0f / 768.0f);
    vp = block_sum(vp, sred) * (1.0f / 768.0f);
    const float inva = rsqrtf(va + 1e-12f);
    const float invp = rsqrtf(vp + 1e-12f);

    #pragma unroll
    for (int t = 0; t < 3; t++) {
        const int j = tid + t * 256;
        out[n * W_F + j] = (a[t] - ma) * inva * gagg[j] + beagg[j]
                         + (p[t] - mp) * invp * gpos[j] + bepos[j];
    }
}

// ---------------------------------------------------------------------------
extern "C" void kernel_launch(void* const* d_in, const int* in_sizes, int n_in,
                              void* d_out, int out_size) {
    const float* q_pos  = (const float*)d_in[0];
    const float* pts    = (const float*)d_in[1];
    const float* feats  = (const float*)d_in[2];
    const float* pos_in = (const float*)d_in[3];
    const float* Wagg   = (const float*)d_in[4];
    const float* bagg   = (const float*)d_in[5];
    const float* gagg   = (const float*)d_in[6];
    const float* beagg  = (const float*)d_in[7];
    const float* Wpos   = (const float*)d_in[8];
    const float* bpos   = (const float*)d_in[9];
    const float* gpos   = (const float*)d_in[10];
    const float* bepos  = (const float*)d_in[11];
    float* out = (float*)d_out;

    pack_kernel<<<(M_P + 255) / 256, 256>>>(pts);
    topk_kernel<<<N_Q, 256>>>(q_pos);

    dim3 ggrid(W_F / BN, N_Q / BM);
    gemm_kernel<<<ggrid, 256>>>(feats, Wagg, bagg);

    ln_kernel<<<N_Q, 256>>>(pos_in, Wpos, bpos, gagg, beagg, gpos, bepos, out);
}

// round 8
// speedup vs baseline: 1.6815x; 1.6815x over previous
#include <cuda_runtime.h>
#include <cuda_bf16.h>
#include <float.h>
#include <stdint.h>

#define N_Q   4096
#define M_P   32768
#define W_F   768
#define K_NN  4
#define R2    0.25f
#define K_TOT (K_NN * W_F)        // 3072

// ---------------- scratch (static device memory; no allocs allowed) --------
__device__ int            g_idx[N_Q * K_NN];
__device__ float          g_aggraw[N_Q * W_F];
__device__ float4         g_pts4[M_P];
__device__ __nv_bfloat16  g_Ah[(size_t)N_Q * K_TOT];   // gathered A, hi plane [4096][3072]
__device__ __nv_bfloat16  g_Al[(size_t)N_Q * K_TOT];   // gathered A, lo plane
__device__ __nv_bfloat16  g_Bh[(size_t)K_TOT * W_F];   // Wagg hi plane [3072][768]
__device__ __nv_bfloat16  g_Bl[(size_t)K_TOT * W_F];   // Wagg lo plane

__device__ __forceinline__ bool pair_less(float d1, int i1, float d2, int i2) {
    return (d1 < d2) || (d1 == d2 && i1 < i2);
}

__device__ __forceinline__ uint32_t smem_u32(const void* p) {
    uint32_t a;
    asm("{ .reg .u64 t; cvta.to.shared.u64 t, %1; cvt.u32.u64 %0, t; }"
        : "=r"(a) : "l"(p));
    return a;
}

// ---------------------------------------------------------------------------
// Kernel 0: pack pts -> {x,y,z,pp}; pp in exact reference association
// (descending FMA — validated R5, FROZEN).
// ---------------------------------------------------------------------------
__global__ __launch_bounds__(256) void pack_kernel(const float* __restrict__ pts) {
    const int j = blockIdx.x * 256 + threadIdx.x;
    if (j < M_P) {
        const float px = pts[j * 3 + 0];
        const float py = pts[j * 3 + 1];
        const float pz = pts[j * 3 + 2];
        const float pp = __fmaf_rn(px, px, __fmaf_rn(py, py, __fmul_rn(pz, pz)));
        g_pts4[j] = make_float4(px, py, pz, pp);
    }
}

// ---------------------------------------------------------------------------
// Kernel 1: top-4 NN per query. Arithmetic FROZEN (R5 bit-exact).
// ---------------------------------------------------------------------------
__global__ __launch_bounds__(256) void topk_kernel(const float* __restrict__ q_pos) {
    const int n   = blockIdx.x;
    const int tid = threadIdx.x;

    const float qx = q_pos[n * 3 + 0];
    const float qy = q_pos[n * 3 + 1];
    const float qz = q_pos[n * 3 + 2];
    const float qq = __fmaf_rn(qx, qx, __fmaf_rn(qy, qy, __fmul_rn(qz, qz)));

    float bd[4] = {FLT_MAX, FLT_MAX, FLT_MAX, FLT_MAX};
    int   bi[4] = {-1, -1, -1, -1};

    #pragma unroll 1
    for (int it = 0; it < M_P / (256 * 4); it++) {
        const int jb = it * (256 * 4) + tid;
        float4 p[4];
        #pragma unroll
        for (int u = 0; u < 4; u++) p[u] = g_pts4[jb + u * 256];

        #pragma unroll
        for (int u = 0; u < 4; u++) {
            const int j = jb + u * 256;
            float dot = __fmul_rn(qx, p[u].x);
            dot = __fmaf_rn(qy, p[u].y, dot);
            dot = __fmaf_rn(qz, p[u].z, dot);
            const float t1 = __fadd_rn(qq, p[u].w);
            const float d2 = __fadd_rn(t1, -__fmul_rn(2.0f, dot));
            if (pair_less(d2, j, bd[3], bi[3])) {
                bd[3] = d2; bi[3] = j;
                #pragma unroll
                for (int q = 3; q > 0; --q) {
                    if (pair_less(bd[q], bi[q], bd[q - 1], bi[q - 1])) {
                        float td = bd[q]; bd[q] = bd[q - 1]; bd[q - 1] = td;
                        int   ti = bi[q]; bi[q] = bi[q - 1]; bi[q - 1] = ti;
                    }
                }
            }
        }
    }

    __shared__ float sd[256 * 4];
    __shared__ int   si[256 * 4];
    #pragma unroll
    for (int k = 0; k < 4; k++) { sd[tid * 4 + k] = bd[k]; si[tid * 4 + k] = bi[k]; }
    __syncthreads();

    for (int s = 128; s > 0; s >>= 1) {
        if (tid < s) {
            float ad[4], xd[4]; int ai[4], xi[4];
            #pragma unroll
            for (int k = 0; k < 4; k++) {
                ad[k] = sd[tid * 4 + k];        ai[k] = si[tid * 4 + k];
                xd[k] = sd[(tid + s) * 4 + k];  xi[k] = si[(tid + s) * 4 + k];
            }
            float rd[4]; int ri[4];
            int ia = 0, ib = 0;
            #pragma unroll
            for (int t = 0; t < 4; t++) {
                bool takeA = pair_less(ad[ia], ai[ia], xd[ib], xi[ib]);
                rd[t] = takeA ? ad[ia] : xd[ib];
                ri[t] = takeA ? ai[ia] : xi[ib];
                if (takeA) ia++; else ib++;
            }
            #pragma unroll
            for (int k = 0; k < 4; k++) { sd[tid * 4 + k] = rd[k]; si[tid * 4 + k] = ri[k]; }
        }
        __syncthreads();
    }

    if (tid == 0) {
        #pragma unroll
        for (int k = 0; k < 4; k++)
            g_idx[n * 4 + k] = (sd[k] <= R2) ? si[k] : -1;
    }
}

// ---------------------------------------------------------------------------
// bf16 split: x = hi + lo (+ ~2^-17 residual)
// ---------------------------------------------------------------------------
__device__ __forceinline__ void bf16_split(float x, __nv_bfloat16& hi, __nv_bfloat16& lo) {
    hi = __float2bfloat16_rn(x);
    lo = __float2bfloat16_rn(x - __bfloat162float(hi));
}

// ---------------------------------------------------------------------------
// Kernel 2a: elementwise split Wagg[3072][768] -> g_Bh/g_Bl (same layout)
// ---------------------------------------------------------------------------
__global__ __launch_bounds__(256) void wsplit_kernel(const float* __restrict__ Wagg) {
    const size_t id = (size_t)blockIdx.x * 256 + threadIdx.x;   // float4 index
    const float4 v = reinterpret_cast<const float4*>(Wagg)[id];
    __nv_bfloat16 h0,h1,h2,h3,l0,l1,l2,l3;
    bf16_split(v.x, h0, l0);
    bf16_split(v.y, h1, l1);
    bf16_split(v.z, h2, l2);
    bf16_split(v.w, h3, l3);
    __nv_bfloat162* ph = reinterpret_cast<__nv_bfloat162*>(g_Bh) + id * 2;
    __nv_bfloat162* pl = reinterpret_cast<__nv_bfloat162*>(g_Bl) + id * 2;
    ph[0] = __nv_bfloat162(h0, h1);
    ph[1] = __nv_bfloat162(h2, h3);
    pl[0] = __nv_bfloat162(l0, l1);
    pl[1] = __nv_bfloat162(l2, l3);
}

// ---------------------------------------------------------------------------
// Kernel 2b: gather + split feats -> g_Ah/g_Al [4096][3072]
// ---------------------------------------------------------------------------
__global__ __launch_bounds__(256) void gather_kernel(const float* __restrict__ feats) {
    const int n = blockIdx.x;
    __shared__ int sl[4];
    if (threadIdx.x < 4) sl[threadIdx.x] = g_idx[n * 4 + threadIdx.x];
    __syncthreads();

    #pragma unroll
    for (int k = 0; k < 4; k++) {
        const int prow = sl[k];
        const int t = threadIdx.x;
        if (t < 192) {
            float4 v = make_float4(0.f, 0.f, 0.f, 0.f);
            if (prow >= 0)
                v = *reinterpret_cast<const float4*>(&feats[(size_t)prow * W_F + t * 4]);
            __nv_bfloat16 h0,h1,h2,h3,l0,l1,l2,l3;
            bf16_split(v.x, h0, l0);
            bf16_split(v.y, h1, l1);
            bf16_split(v.z, h2, l2);
            bf16_split(v.w, h3, l3);
            const size_t off = (size_t)n * K_TOT + k * W_F + t * 4;
            __nv_bfloat162* ph = reinterpret_cast<__nv_bfloat162*>(&g_Ah[off]);
            __nv_bfloat162* pl = reinterpret_cast<__nv_bfloat162*>(&g_Al[off]);
            ph[0] = __nv_bfloat162(h0, h1);
            ph[1] = __nv_bfloat162(h2, h3);
            pl[0] = __nv_bfloat162(l0, l1);
            pl[1] = __nv_bfloat162(l2, l3);
        }
    }
}

// ---------------------------------------------------------------------------
// Kernel 3: bf16 mma.sync GEMM (sm_80-class path; no tcgen05 on this target)
//   C[4096,768] = Ah·Bh^T?  — logically C = A · W, A[4096,3072], W[3072,768]
//   3 plane products: Ah*Bh + Ah*Bl + Al*Bh, fp32 accum.
// CTA 128x64, K-tile 32, 8 warps (4m x 2n, warp tile 32x32), 3-stage cp.async.
// ---------------------------------------------------------------------------
#define CTA_M 128
#define CTA_N 64
#define CTA_K 32
#define STAGES 3
#define NKIT (K_TOT / CTA_K)            // 96
#define LDA_B 80                        // 64B data + 16B pad
#define LDB_B 144                       // 128B data + 16B pad
#define A_PLANE_B (CTA_M * LDA_B)       // 10240
#define B_PLANE_B (CTA_K * LDB_B)       // 4608
#define STAGE_B (2 * A_PLANE_B + 2 * B_PLANE_B)   // 29696
#define GEMM_SMEM (STAGES * STAGE_B)              // 89088

#define CP_ASYNC16(saddr, gaddr) \
    asm volatile("cp.async.cg.shared.global [%0], [%1], 16;" :: "r"(saddr), "l"(gaddr))
#define CP_COMMIT()  asm volatile("cp.async.commit_group;" ::: "memory")
#define CP_WAIT(n)   asm volatile("cp.async.wait_group %0;" :: "n"(n) : "memory")

__device__ __forceinline__ void ldsm_x4(uint32_t& r0, uint32_t& r1, uint32_t& r2,
                                        uint32_t& r3, uint32_t addr) {
    asm volatile("ldmatrix.sync.aligned.m8n8.x4.shared.b16 {%0,%1,%2,%3}, [%4];"
                 : "=r"(r0), "=r"(r1), "=r"(r2), "=r"(r3) : "r"(addr));
}
__device__ __forceinline__ void ldsm_x4_t(uint32_t& r0, uint32_t& r1, uint32_t& r2,
                                          uint32_t& r3, uint32_t addr) {
    asm volatile("ldmatrix.sync.aligned.m8n8.x4.trans.shared.b16 {%0,%1,%2,%3}, [%4];"
                 : "=r"(r0), "=r"(r1), "=r"(r2), "=r"(r3) : "r"(addr));
}
__device__ __forceinline__ void mma16816(float* c, const uint32_t* a, const uint32_t* b) {
    asm volatile(
        "mma.sync.aligned.m16n8k16.row.col.f32.bf16.bf16.f32 "
        "{%0,%1,%2,%3}, {%4,%5,%6,%7}, {%8,%9}, {%0,%1,%2,%3};"
        : "+f"(c[0]), "+f"(c[1]), "+f"(c[2]), "+f"(c[3])
        : "r"(a[0]), "r"(a[1]), "r"(a[2]), "r"(a[3]), "r"(b[0]), "r"(b[1]));
}

// load one stage: A planes (gathered rows bm..bm+127, k window) + B planes
__device__ __forceinline__ void load_stage(char* smem, int slot, int kt,
                                           int bm, int bn, int tid) {
    const uint32_t sbase = smem_u32(smem) + (uint32_t)slot * STAGE_B;
    const char* gAh = reinterpret_cast<const char*>(g_Ah);
    const char* gAl = reinterpret_cast<const char*>(g_Al);
    const char* gBh = reinterpret_cast<const char*>(g_Bh);
    const char* gBl = reinterpret_cast<const char*>(g_Bl);

    // A: 128 rows x 64B per plane = 512 x 16B chunks; 2 per thread per plane
    #pragma unroll
    for (int i = 0; i < 2; i++) {
        const int id  = tid + i * 256;
        const int row = id >> 2;
        const int col = (id & 3) * 16;
        const size_t goff = ((size_t)(bm + row) * K_TOT + kt) * 2 + col;
        CP_ASYNC16(sbase + 0 * A_PLANE_B + row * LDA_B + col, gAh + goff);
        CP_ASYNC16(sbase + 1 * A_PLANE_B + row * LDA_B + col, gAl + goff);
    }
    // B: 32 rows x 128B per plane = 256 x 16B chunks; 1 per thread per plane
    {
        const int row = tid >> 3;
        const int col = (tid & 7) * 16;
        const size_t goff = ((size_t)(kt + row) * W_F + bn) * 2 + col;
        CP_ASYNC16(sbase + 2 * A_PLANE_B + 0 * B_PLANE_B + row * LDB_B + col, gBh + goff);
        CP_ASYNC16(sbase + 2 * A_PLANE_B + 1 * B_PLANE_B + row * LDB_B + col, gBl + goff);
    }
}

__global__ __launch_bounds__(256) void gemm_mma_kernel(const float* __restrict__ bagg) {
    extern __shared__ char smem[];
    const int tid  = threadIdx.x;
    const int wid  = tid >> 5;
    const int lane = tid & 31;
    const int bm = blockIdx.y * CTA_M;
    const int bn = blockIdx.x * CTA_N;
    const int wm = (wid & 3) * 32;     // warp m offset in CTA
    const int wn = (wid >> 2) * 32;    // warp n offset in CTA

    float c[2][4][4];                  // [m16 frag][n8 frag][4]
    #pragma unroll
    for (int mi = 0; mi < 2; mi++)
        #pragma unroll
        for (int ni = 0; ni < 4; ni++)
            #pragma unroll
            for (int r = 0; r < 4; r++) c[mi][ni][r] = 0.0f;

    // prologue
    load_stage(smem, 0, 0, bm, bn, tid); CP_COMMIT();
    load_stage(smem, 1, CTA_K, bm, bn, tid); CP_COMMIT();

    const uint32_t sb = smem_u32(smem);
    // per-thread ldmatrix address components
    const int a_row = wm + (lane & 15);          // + mi*16
    const int a_col = (lane >> 4) * 16;          // + k16*32
    const int b_row = (lane & 7) + ((lane >> 3) & 1) * 8;   // + k16*16
    const int b_col = wn + (lane >> 4) * 8;      // + nhalf*16

    #pragma unroll 1
    for (int it = 0; it < NKIT; it++) {
        CP_WAIT(1);
        __syncthreads();

        if (it + STAGES - 1 < NKIT)
            load_stage(smem, (it + STAGES - 1) % STAGES, (it + STAGES - 1) * CTA_K,
                       bm, bn, tid);
        CP_COMMIT();

        const uint32_t st = sb + (uint32_t)(it % STAGES) * STAGE_B;
        const uint32_t sAh = st;
        const uint32_t sAl = st + A_PLANE_B;
        const uint32_t sBh = st + 2 * A_PLANE_B;
        const uint32_t sBl = sBh + B_PLANE_B;

        #pragma unroll
        for (int k16 = 0; k16 < 2; k16++) {
            uint32_t ah[2][4], al[2][4];
            #pragma unroll
            for (int mi = 0; mi < 2; mi++) {
                const uint32_t off = (uint32_t)((a_row + mi * 16) * LDA_B
                                                + k16 * 32 + a_col);
                ldsm_x4(ah[mi][0], ah[mi][1], ah[mi][2], ah[mi][3], sAh + off);
                ldsm_x4(al[mi][0], al[mi][1], al[mi][2], al[mi][3], sAl + off);
            }
            uint32_t bh[4][2], bl[4][2];
            #pragma unroll
            for (int nh = 0; nh < 2; nh++) {
                const uint32_t off = (uint32_t)((k16 * 16 + b_row) * LDB_B
                                                + (b_col + nh * 16) * 2);
                uint32_t r0, r1, r2, r3;
                ldsm_x4_t(r0, r1, r2, r3, sBh + off);
                bh[nh * 2 + 0][0] = r0; bh[nh * 2 + 0][1] = r1;
                bh[nh * 2 + 1][0] = r2; bh[nh * 2 + 1][1] = r3;
                ldsm_x4_t(r0, r1, r2, r3, sBl + off);
                bl[nh * 2 + 0][0] = r0; bl[nh * 2 + 0][1] = r1;
                bl[nh * 2 + 1][0] = r2; bl[nh * 2 + 1][1] = r3;
            }
            #pragma unroll
            for (int mi = 0; mi < 2; mi++)
                #pragma unroll
                for (int ni = 0; ni < 4; ni++) {
                    mma16816(c[mi][ni], ah[mi], bh[ni]);   // hi*hi
                    mma16816(c[mi][ni], ah[mi], bl[ni]);   // hi*lo
                    mma16816(c[mi][ni], al[mi], bh[ni]);   // lo*hi
                }
        }
        __syncthreads();
    }

    // epilogue: c frag (t/4 = row-in-8, t%4*2 = col pair), + bias
    #pragma unroll
    for (int mi = 0; mi < 2; mi++) {
        #pragma unroll
        for (int ni = 0; ni < 4; ni++) {
            const int row0 = bm + wm + mi * 16 + (lane >> 2);
            const int col  = bn + wn + ni * 8 + (lane & 3) * 2;
            const float bx = bagg[col], by = bagg[col + 1];
            float2 o0 = make_float2(c[mi][ni][0] + bx, c[mi][ni][1] + by);
            float2 o1 = make_float2(c[mi][ni][2] + bx, c[mi][ni][3] + by);
            *reinterpret_cast<float2*>(&g_aggraw[(size_t)row0 * W_F + col]) = o0;
            *reinterpret_cast<float2*>(&g_aggraw[(size_t)(row0 + 8) * W_F + col]) = o1;
        }
    }
}

// ---------------------------------------------------------------------------
// Kernel 4: pos embedding GEMV (K=6) + two LayerNorms + add.
// ---------------------------------------------------------------------------
__device__ __forceinline__ float block_sum(float v, float* sbuf) {
    __syncthreads();
    #pragma unroll
    for (int o = 16; o > 0; o >>= 1) v += __shfl_xor_sync(0xffffffffu, v, o);
    const int wid = threadIdx.x >> 5, lane = threadIdx.x & 31;
    if (lane == 0) sbuf[wid] = v;
    __syncthreads();
    if (wid == 0) {
        float x = (lane < 8) ? sbuf[lane] : 0.0f;
        #pragma unroll
        for (int o = 4; o > 0; o >>= 1) x += __shfl_xor_sync(0xffffffffu, x, o);
        if (lane == 0) sbuf[0] = x;
    }
    __syncthreads();
    return sbuf[0];
}

__global__ __launch_bounds__(256) void ln_kernel(const float* __restrict__ pos_in,
                                                 const float* __restrict__ Wpos,
                                                 const float* __restrict__ bpos,
                                                 const float* __restrict__ gagg,
                                                 const float* __restrict__ beagg,
                                                 const float* __restrict__ gpos,
                                                 const float* __restrict__ bepos,
                                                 float* __restrict__ out) {
    const int n   = blockIdx.x;
    const int tid = threadIdx.x;
    __shared__ float pin[6];
    __shared__ float sred[32];
    if (tid < 6) pin[tid] = pos_in[n * 6 + tid];
    __syncthreads();

    float a[3], p[3];
    float sa = 0.f, sp = 0.f;
    #pragma unroll
    for (int t = 0; t < 3; t++) {
        const int j = tid + t * 256;
        a[t] = g_aggraw[n * W_F + j];
        float pv = bpos[j];
        #pragma unroll
        for (int i = 0; i < 6; i++) pv += pin[i] * Wpos[i * W_F + j];
        p[t] = pv;
        sa += a[t]; sp += p[t];
    }
    const float ma = block_sum(sa, sred) * (1.0f / 768.0f);
    const float mp = block_sum(sp, sred) * (1.0f / 768.0f);

    float va = 0.f, vp = 0.f;
    #pragma unroll
    for (int t = 0; t < 3; t++) {
        const float da = a[t] - ma; va += da * da;
        const float dp = p[t] - mp; vp += dp * dp;
    }
    va = block_sum(va, sred) * (1.0f / 768.0f);
    vp = block_sum(vp, sred) * (1.0f / 768.0f);
    const float inva = rsqrtf(va + 1e-12f);
    const float invp = rsqrtf(vp + 1e-12f);

    #pragma unroll
    for (int t = 0; t < 3; t++) {
        const int j = tid + t * 256;
        out[n * W_F + j] = (a[t] - ma) * inva * gagg[j] + beagg[j]
                         + (p[t] - mp) * invp * gpos[j] + bepos[j];
    }
}

// ---------------------------------------------------------------------------
extern "C" void kernel_launch(void* const* d_in, const int* in_sizes, int n_in,
                              void* d_out, int out_size) {
    const float* q_pos  = (const float*)d_in[0];
    const float* pts    = (const float*)d_in[1];
    const float* feats  = (const float*)d_in[2];
    const float* pos_in = (const float*)d_in[3];
    const float* Wagg   = (const float*)d_in[4];
    const float* bagg   = (const float*)d_in[5];
    const float* gagg   = (const float*)d_in[6];
    const float* beagg  = (const float*)d_in[7];
    const float* Wpos   = (const float*)d_in[8];
    const float* bpos   = (const float*)d_in[9];
    const float* gpos   = (const float*)d_in[10];
    const float* bepos  = (const float*)d_in[11];
    float* out = (float*)d_out;

    static int smem_set = 0;
    if (!smem_set) {
        cudaFuncSetAttribute(gemm_mma_kernel,
                             cudaFuncAttributeMaxDynamicSharedMemorySize, GEMM_SMEM);
        smem_set = 1;
    }

    pack_kernel<<<(M_P + 255) / 256, 256>>>(pts);
    topk_kernel<<<N_Q, 256>>>(q_pos);

    wsplit_kernel<<<(K_TOT * W_F / 4) / 256, 256>>>(Wagg);
    gather_kernel<<<N_Q, 256>>>(feats);

    dim3 ggrid(W_F / CTA_N, N_Q / CTA_M);            // 12 x 32 = 384 CTAs
    gemm_mma_kernel<<<ggrid, 256, GEMM_SMEM>>>(bagg);

    ln_kernel<<<N_Q, 256>>>(pos_in, Wpos, bpos, gagg, beagg, gpos, bepos, out);
}

// round 9
// speedup vs baseline: 2.3184x; 1.3788x over previous
#include <cuda_runtime.h>
#include <cuda_bf16.h>
#include <float.h>
#include <stdint.h>

#define N_Q   4096
#define M_P   32768
#define W_F   768
#define K_NN  4
#define R2    0.25f
#define K_TOT (K_NN * W_F)        // 3072
#define IDX_SENT 0x7FFFFFFF

// ---------------- scratch (static device memory; no allocs allowed) --------
__device__ int            g_idx[N_Q * K_NN];
__device__ float          g_aggraw[N_Q * W_F];
__device__ float4         g_pts4[M_P];
__device__ __nv_bfloat16  g_Ah[(size_t)N_Q * K_TOT];   // gathered A, hi plane
__device__ __nv_bfloat16  g_Al[(size_t)N_Q * K_TOT];   // gathered A, lo plane
__device__ __nv_bfloat16  g_Bh[(size_t)K_TOT * W_F];   // Wagg hi plane [3072][768]
__device__ __nv_bfloat16  g_Bl[(size_t)K_TOT * W_F];   // Wagg lo plane

__device__ __forceinline__ bool pair_less(float d1, int i1, float d2, int i2) {
    return (d1 < d2) || (d1 == d2 && i1 < i2);
}

__device__ __forceinline__ uint32_t smem_u32(const void* p) {
    uint32_t a;
    asm("{ .reg .u64 t; cvta.to.shared.u64 t, %1; cvt.u32.u64 %0, t; }"
        : "=r"(a) : "l"(p));
    return a;
}

// ---------------------------------------------------------------------------
// Kernel 0: pack pts -> {x,y,z,pp}; pp in exact reference association
// (descending FMA — validated R5, FROZEN).
// ---------------------------------------------------------------------------
__global__ __launch_bounds__(256) void pack_kernel(const float* __restrict__ pts) {
    const int j = blockIdx.x * 256 + threadIdx.x;
    if (j < M_P) {
        const float px = pts[j * 3 + 0];
        const float py = pts[j * 3 + 1];
        const float pz = pts[j * 3 + 2];
        const float pp = __fmaf_rn(px, px, __fmaf_rn(py, py, __fmul_rn(pz, pz)));
        g_pts4[j] = make_float4(px, py, pz, pp);
    }
}

// ---------------------------------------------------------------------------
// Kernel 1: top-4 NN per query. Arithmetic FROZEN (R5 bit-exact).
// Radius-pruned: list seeded with (R2, IDX_SENT) sentinels; only in-radius
// points can enter (out-of-radius neighbors contribute zero rows anyway).
// Guard branch taken ~0.05% of evals -> insert network cost vanishes.
// ---------------------------------------------------------------------------
__global__ __launch_bounds__(256) void topk_kernel(const float* __restrict__ q_pos) {
    const int n   = blockIdx.x;
    const int tid = threadIdx.x;

    const float qx = q_pos[n * 3 + 0];
    const float qy = q_pos[n * 3 + 1];
    const float qz = q_pos[n * 3 + 2];
    const float qq = __fmaf_rn(qx, qx, __fmaf_rn(qy, qy, __fmul_rn(qz, qz)));

    float bd[4] = {R2, R2, R2, R2};
    int   bi[4] = {IDX_SENT, IDX_SENT, IDX_SENT, IDX_SENT};

    #pragma unroll 1
    for (int it = 0; it < M_P / (256 * 4); it++) {
        const int jb = it * (256 * 4) + tid;
        float4 p[4];
        #pragma unroll
        for (int u = 0; u < 4; u++) p[u] = g_pts4[jb + u * 256];

        #pragma unroll
        for (int u = 0; u < 4; u++) {
            const int j = jb + u * 256;
            float dot = __fmul_rn(qx, p[u].x);
            dot = __fmaf_rn(qy, p[u].y, dot);
            dot = __fmaf_rn(qz, p[u].z, dot);
            const float t1 = __fadd_rn(qq, p[u].w);
            const float d2 = __fadd_rn(t1, -__fmul_rn(2.0f, dot));
            if (d2 <= bd[3]) {                     // rare (~0.05%): real branch
                if (pair_less(d2, j, bd[3], bi[3])) {
                    bd[3] = d2; bi[3] = j;
                    #pragma unroll
                    for (int q = 3; q > 0; --q) {
                        if (pair_less(bd[q], bi[q], bd[q - 1], bi[q - 1])) {
                            float td = bd[q]; bd[q] = bd[q - 1]; bd[q - 1] = td;
                            int   ti = bi[q]; bi[q] = bi[q - 1]; bi[q - 1] = ti;
                        }
                    }
                }
            }
        }
    }

    __shared__ float sd[256 * 4];
    __shared__ int   si[256 * 4];
    #pragma unroll
    for (int k = 0; k < 4; k++) { sd[tid * 4 + k] = bd[k]; si[tid * 4 + k] = bi[k]; }
    __syncthreads();

    // Tree merge of sorted 4-lists (sentinels sort last).
    for (int s = 128; s > 0; s >>= 1) {
        if (tid < s) {
            float ad[4], xd[4]; int ai[4], xi[4];
            #pragma unroll
            for (int k = 0; k < 4; k++) {
                ad[k] = sd[tid * 4 + k];        ai[k] = si[tid * 4 + k];
                xd[k] = sd[(tid + s) * 4 + k];  xi[k] = si[(tid + s) * 4 + k];
            }
            float rd[4]; int ri[4];
            int ia = 0, ib = 0;
            #pragma unroll
            for (int t = 0; t < 4; t++) {
                bool takeA = pair_less(ad[ia], ai[ia], xd[ib], xi[ib]);
                rd[t] = takeA ? ad[ia] : xd[ib];
                ri[t] = takeA ? ai[ia] : xi[ib];
                if (takeA) ia++; else ib++;
            }
            #pragma unroll
            for (int k = 0; k < 4; k++) { sd[tid * 4 + k] = rd[k]; si[tid * 4 + k] = ri[k]; }
        }
        __syncthreads();
    }

    if (tid == 0) {
        #pragma unroll
        for (int k = 0; k < 4; k++)
            g_idx[n * 4 + k] = (si[k] == IDX_SENT) ? -1 : si[k];
    }
}

// ---------------------------------------------------------------------------
// bf16 split: x = hi + lo (+ ~2^-17 residual)
// ---------------------------------------------------------------------------
__device__ __forceinline__ void bf16_split(float x, __nv_bfloat16& hi, __nv_bfloat16& lo) {
    hi = __float2bfloat16_rn(x);
    lo = __float2bfloat16_rn(x - __bfloat162float(hi));
}

// ---------------------------------------------------------------------------
// Kernel 2a: elementwise split Wagg[3072][768] -> g_Bh/g_Bl (same layout)
// ---------------------------------------------------------------------------
__global__ __launch_bounds__(256) void wsplit_kernel(const float* __restrict__ Wagg) {
    const size_t id = (size_t)blockIdx.x * 256 + threadIdx.x;   // float4 index
    const float4 v = reinterpret_cast<const float4*>(Wagg)[id];
    __nv_bfloat16 h0,h1,h2,h3,l0,l1,l2,l3;
    bf16_split(v.x, h0, l0);
    bf16_split(v.y, h1, l1);
    bf16_split(v.z, h2, l2);
    bf16_split(v.w, h3, l3);
    __nv_bfloat162* ph = reinterpret_cast<__nv_bfloat162*>(g_Bh) + id * 2;
    __nv_bfloat162* pl = reinterpret_cast<__nv_bfloat162*>(g_Bl) + id * 2;
    ph[0] = __nv_bfloat162(h0, h1);
    ph[1] = __nv_bfloat162(h2, h3);
    pl[0] = __nv_bfloat162(l0, l1);
    pl[1] = __nv_bfloat162(l2, l3);
}

// ---------------------------------------------------------------------------
// Kernel 2b: gather + split feats -> g_Ah/g_Al [4096][3072]
// ---------------------------------------------------------------------------
__global__ __launch_bounds__(256) void gather_kernel(const float* __restrict__ feats) {
    const int n = blockIdx.x;
    __shared__ int sl[4];
    if (threadIdx.x < 4) sl[threadIdx.x] = g_idx[n * 4 + threadIdx.x];
    __syncthreads();

    #pragma unroll
    for (int k = 0; k < 4; k++) {
        const int prow = sl[k];
        const int t = threadIdx.x;
        if (t < 192) {
            float4 v = make_float4(0.f, 0.f, 0.f, 0.f);
            if (prow >= 0)
                v = *reinterpret_cast<const float4*>(&feats[(size_t)prow * W_F + t * 4]);
            __nv_bfloat16 h0,h1,h2,h3,l0,l1,l2,l3;
            bf16_split(v.x, h0, l0);
            bf16_split(v.y, h1, l1);
            bf16_split(v.z, h2, l2);
            bf16_split(v.w, h3, l3);
            const size_t off = (size_t)n * K_TOT + k * W_F + t * 4;
            __nv_bfloat162* ph = reinterpret_cast<__nv_bfloat162*>(&g_Ah[off]);
            __nv_bfloat162* pl = reinterpret_cast<__nv_bfloat162*>(&g_Al[off]);
            ph[0] = __nv_bfloat162(h0, h1);
            ph[1] = __nv_bfloat162(h2, h3);
            pl[0] = __nv_bfloat162(l0, l1);
            pl[1] = __nv_bfloat162(l2, l3);
        }
    }
}

// ---------------------------------------------------------------------------
// Kernel 3: bf16 mma.sync GEMM — C = A·W, 3 plane products, fp32 accum.
// CTA 128x64, K-tile 32, 8 warps (4m x 2n), 3-stage cp.async. (unchanged R8)
// ---------------------------------------------------------------------------
#define CTA_M 128
#define CTA_N 64
#define CTA_K 32
#define STAGES 3
#define NKIT (K_TOT / CTA_K)            // 96
#define LDA_B 80
#define LDB_B 144
#define A_PLANE_B (CTA_M * LDA_B)
#define B_PLANE_B (CTA_K * LDB_B)
#define STAGE_B (2 * A_PLANE_B + 2 * B_PLANE_B)
#define GEMM_SMEM (STAGES * STAGE_B)

#define CP_ASYNC16(saddr, gaddr) \
    asm volatile("cp.async.cg.shared.global [%0], [%1], 16;" :: "r"(saddr), "l"(gaddr))
#define CP_COMMIT()  asm volatile("cp.async.commit_group;" ::: "memory")
#define CP_WAIT(n)   asm volatile("cp.async.wait_group %0;" :: "n"(n) : "memory")

__device__ __forceinline__ void ldsm_x4(uint32_t& r0, uint32_t& r1, uint32_t& r2,
                                        uint32_t& r3, uint32_t addr) {
    asm volatile("ldmatrix.sync.aligned.m8n8.x4.shared.b16 {%0,%1,%2,%3}, [%4];"
                 : "=r"(r0), "=r"(r1), "=r"(r2), "=r"(r3) : "r"(addr));
}
__device__ __forceinline__ void ldsm_x4_t(uint32_t& r0, uint32_t& r1, uint32_t& r2,
                                          uint32_t& r3, uint32_t addr) {
    asm volatile("ldmatrix.sync.aligned.m8n8.x4.trans.shared.b16 {%0,%1,%2,%3}, [%4];"
                 : "=r"(r0), "=r"(r1), "=r"(r2), "=r"(r3) : "r"(addr));
}
__device__ __forceinline__ void mma16816(float* c, const uint32_t* a, const uint32_t* b) {
    asm volatile(
        "mma.sync.aligned.m16n8k16.row.col.f32.bf16.bf16.f32 "
        "{%0,%1,%2,%3}, {%4,%5,%6,%7}, {%8,%9}, {%0,%1,%2,%3};"
        : "+f"(c[0]), "+f"(c[1]), "+f"(c[2]), "+f"(c[3])
        : "r"(a[0]), "r"(a[1]), "r"(a[2]), "r"(a[3]), "r"(b[0]), "r"(b[1]));
}

__device__ __forceinline__ void load_stage(char* smem, int slot, int kt,
                                           int bm, int bn, int tid) {
    const uint32_t sbase = smem_u32(smem) + (uint32_t)slot * STAGE_B;
    const char* gAh = reinterpret_cast<const char*>(g_Ah);
    const char* gAl = reinterpret_cast<const char*>(g_Al);
    const char* gBh = reinterpret_cast<const char*>(g_Bh);
    const char* gBl = reinterpret_cast<const char*>(g_Bl);

    #pragma unroll
    for (int i = 0; i < 2; i++) {
        const int id  = tid + i * 256;
        const int row = id >> 2;
        const int col = (id & 3) * 16;
        const size_t goff = ((size_t)(bm + row) * K_TOT + kt) * 2 + col;
        CP_ASYNC16(sbase + 0 * A_PLANE_B + row * LDA_B + col, gAh + goff);
        CP_ASYNC16(sbase + 1 * A_PLANE_B + row * LDA_B + col, gAl + goff);
    }
    {
        const int row = tid >> 3;
        const int col = (tid & 7) * 16;
        const size_t goff = ((size_t)(kt + row) * W_F + bn) * 2 + col;
        CP_ASYNC16(sbase + 2 * A_PLANE_B + 0 * B_PLANE_B + row * LDB_B + col, gBh + goff);
        CP_ASYNC16(sbase + 2 * A_PLANE_B + 1 * B_PLANE_B + row * LDB_B + col, gBl + goff);
    }
}

__global__ __launch_bounds__(256) void gemm_mma_kernel(const float* __restrict__ bagg) {
    extern __shared__ char smem[];
    const int tid  = threadIdx.x;
    const int wid  = tid >> 5;
    const int lane = tid & 31;
    const int bm = blockIdx.y * CTA_M;
    const int bn = blockIdx.x * CTA_N;
    const int wm = (wid & 3) * 32;
    const int wn = (wid >> 2) * 32;

    float c[2][4][4];
    #pragma unroll
    for (int mi = 0; mi < 2; mi++)
        #pragma unroll
        for (int ni = 0; ni < 4; ni++)
            #pragma unroll
            for (int r = 0; r < 4; r++) c[mi][ni][r] = 0.0f;

    load_stage(smem, 0, 0, bm, bn, tid); CP_COMMIT();
    load_stage(smem, 1, CTA_K, bm, bn, tid); CP_COMMIT();

    const uint32_t sb = smem_u32(smem);
    const int a_row = wm + (lane & 15);
    const int a_col = (lane >> 4) * 16;
    const int b_row = (lane & 7) + ((lane >> 3) & 1) * 8;
    const int b_col = wn + (lane >> 4) * 8;

    #pragma unroll 1
    for (int it = 0; it < NKIT; it++) {
        CP_WAIT(1);
        __syncthreads();

        if (it + STAGES - 1 < NKIT)
            load_stage(smem, (it + STAGES - 1) % STAGES, (it + STAGES - 1) * CTA_K,
                       bm, bn, tid);
        CP_COMMIT();

        const uint32_t st = sb + (uint32_t)(it % STAGES) * STAGE_B;
        const uint32_t sAh = st;
        const uint32_t sAl = st + A_PLANE_B;
        const uint32_t sBh = st + 2 * A_PLANE_B;
        const uint32_t sBl = sBh + B_PLANE_B;

        #pragma unroll
        for (int k16 = 0; k16 < 2; k16++) {
            uint32_t ah[2][4], al[2][4];
            #pragma unroll
            for (int mi = 0; mi < 2; mi++) {
                const uint32_t off = (uint32_t)((a_row + mi * 16) * LDA_B
                                                + k16 * 32 + a_col);
                ldsm_x4(ah[mi][0], ah[mi][1], ah[mi][2], ah[mi][3], sAh + off);
                ldsm_x4(al[mi][0], al[mi][1], al[mi][2], al[mi][3], sAl + off);
            }
            uint32_t bh[4][2], bl[4][2];
            #pragma unroll
            for (int nh = 0; nh < 2; nh++) {
                const uint32_t off = (uint32_t)((k16 * 16 + b_row) * LDB_B
                                                + (b_col + nh * 16) * 2);
                uint32_t r0, r1, r2, r3;
                ldsm_x4_t(r0, r1, r2, r3, sBh + off);
                bh[nh * 2 + 0][0] = r0; bh[nh * 2 + 0][1] = r1;
                bh[nh * 2 + 1][0] = r2; bh[nh * 2 + 1][1] = r3;
                ldsm_x4_t(r0, r1, r2, r3, sBl + off);
                bl[nh * 2 + 0][0] = r0; bl[nh * 2 + 0][1] = r1;
                bl[nh * 2 + 1][0] = r2; bl[nh * 2 + 1][1] = r3;
            }
            #pragma unroll
            for (int mi = 0; mi < 2; mi++)
                #pragma unroll
                for (int ni = 0; ni < 4; ni++) {
                    mma16816(c[mi][ni], ah[mi], bh[ni]);
                    mma16816(c[mi][ni], ah[mi], bl[ni]);
                    mma16816(c[mi][ni], al[mi], bh[ni]);
                }
        }
        __syncthreads();
    }

    #pragma unroll
    for (int mi = 0; mi < 2; mi++) {
        #pragma unroll
        for (int ni = 0; ni < 4; ni++) {
            const int row0 = bm + wm + mi * 16 + (lane >> 2);
            const int col  = bn + wn + ni * 8 + (lane & 3) * 2;
            const float bx = bagg[col], by = bagg[col + 1];
            float2 o0 = make_float2(c[mi][ni][0] + bx, c[mi][ni][1] + by);
            float2 o1 = make_float2(c[mi][ni][2] + bx, c[mi][ni][3] + by);
            *reinterpret_cast<float2*>(&g_aggraw[(size_t)row0 * W_F + col]) = o0;
            *reinterpret_cast<float2*>(&g_aggraw[(size_t)(row0 + 8) * W_F + col]) = o1;
        }
    }
}

// ---------------------------------------------------------------------------
// Kernel 4: pos embedding GEMV (K=6) + two LayerNorms + add.
// ---------------------------------------------------------------------------
__device__ __forceinline__ float block_sum(float v, float* sbuf) {
    __syncthreads();
    #pragma unroll
    for (int o = 16; o > 0; o >>= 1) v += __shfl_xor_sync(0xffffffffu, v, o);
    const int wid = threadIdx.x >> 5, lane = threadIdx.x & 31;
    if (lane == 0) sbuf[wid] = v;
    __syncthreads();
    if (wid == 0) {
        float x = (lane < 8) ? sbuf[lane] : 0.0f;
        #pragma unroll
        for (int o = 4; o > 0; o >>= 1) x += __shfl_xor_sync(0xffffffffu, x, o);
        if (lane == 0) sbuf[0] = x;
    }
    __syncthreads();
    return sbuf[0];
}

__global__ __launch_bounds__(256) void ln_kernel(const float* __restrict__ pos_in,
                                                 const float* __restrict__ Wpos,
                                                 const float* __restrict__ bpos,
                                                 const float* __restrict__ gagg,
                                                 const float* __restrict__ beagg,
                                                 const float* __restrict__ gpos,
                                                 const float* __restrict__ bepos,
                                                 float* __restrict__ out) {
    const int n   = blockIdx.x;
    const int tid = threadIdx.x;
    __shared__ float pin[6];
    __shared__ float sred[32];
    if (tid < 6) pin[tid] = pos_in[n * 6 + tid];
    __syncthreads();

    float a[3], p[3];
    float sa = 0.f, sp = 0.f;
    #pragma unroll
    for (int t = 0; t < 3; t++) {
        const int j = tid + t * 256;
        a[t] = g_aggraw[n * W_F + j];
        float pv = bpos[j];
        #pragma unroll
        for (int i = 0; i < 6; i++) pv += pin[i] * Wpos[i * W_F + j];
        p[t] = pv;
        sa += a[t]; sp += p[t];
    }
    const float ma = block_sum(sa, sred) * (1.0f / 768.0f);
    const float mp = block_sum(sp, sred) * (1.0f / 768.0f);

    float va = 0.f, vp = 0.f;
    #pragma unroll
    for (int t = 0; t < 3; t++) {
        const float da = a[t] - ma; va += da * da;
        const float dp = p[t] - mp; vp += dp * dp;
    }
    va = block_sum(va, sred) * (1.0f / 768.0f);
    vp = block_sum(vp, sred) * (1.0f / 768.0f);
    const float inva = rsqrtf(va + 1e-12f);
    const float invp = rsqrtf(vp + 1e-12f);

    #pragma unroll
    for (int t = 0; t < 3; t++) {
        const int j = tid + t * 256;
        out[n * W_F + j] = (a[t] - ma) * inva * gagg[j] + beagg[j]
                         + (p[t] - mp) * invp * gpos[j] + bepos[j];
    }
}

// ---------------------------------------------------------------------------
extern "C" void kernel_launch(void* const* d_in, const int* in_sizes, int n_in,
                              void* d_out, int out_size) {
    const float* q_pos  = (const float*)d_in[0];
    const float* pts    = (const float*)d_in[1];
    const float* feats  = (const float*)d_in[2];
    const float* pos_in = (const float*)d_in[3];
    const float* Wagg   = (const float*)d_in[4];
    const float* bagg   = (const float*)d_in[5];
    const float* gagg   = (const float*)d_in[6];
    const float* beagg  = (const float*)d_in[7];
    const float* Wpos   = (const float*)d_in[8];
    const float* bpos   = (const float*)d_in[9];
    const float* gpos   = (const float*)d_in[10];
    const float* bepos  = (const float*)d_in[11];
    float* out = (float*)d_out;

    static int smem_set = 0;
    if (!smem_set) {
        cudaFuncSetAttribute(gemm_mma_kernel,
                             cudaFuncAttributeMaxDynamicSharedMemorySize, GEMM_SMEM);
        smem_set = 1;
    }

    pack_kernel<<<(M_P + 255) / 256, 256>>>(pts);
    topk_kernel<<<N_Q, 256>>>(q_pos);

    wsplit_kernel<<<(K_TOT * W_F / 4) / 256, 256>>>(Wagg);
    gather_kernel<<<N_Q, 256>>>(feats);

    dim3 ggrid(W_F / CTA_N, N_Q / CTA_M);            // 12 x 32 = 384 CTAs
    gemm_mma_kernel<<<ggrid, 256, GEMM_SMEM>>>(bagg);

    ln_kernel<<<N_Q, 256>>>(pos_in, Wpos, bpos, gagg, beagg, gpos, bepos, out);
}